// round 5
// baseline (speedup 1.0000x reference)
#include <cuda_runtime.h>

#define T_STEPS 1024
#define BATCH   256
#define HID     512
#define NBLK    256
#define THREADS 256
#define KHALF   (HID / 2)         // 256 k per split
#define UPB     2                 // hidden units per block
#define GROWS   8                 // gate rows per block (2 units x 4 gates)

// Persistent device state (allocation-free scratch)
__device__ float g_h[2][HID * BATCH];   // h[k][b]
__device__ float g_zxT[64 * BATCH];     // zx transposed [col][b]
__device__ float g_zeT[16 * BATCH];     // ze logits transposed [col][b]
__device__ unsigned int g_cnt;          // zero-initialized
__device__ unsigned int g_gen;          // zero-initialized

// ---------- helpers ----------
__device__ __forceinline__ void ffma2(unsigned long long& d,
                                      unsigned long long a,
                                      unsigned long long b) {
    asm("fma.rn.f32x2 %0, %1, %2, %0;" : "+l"(d) : "l"(a), "l"(b));
}
__device__ __forceinline__ unsigned long long addf32x2(unsigned long long a,
                                                       unsigned long long b) {
    unsigned long long r;
    asm("add.rn.f32x2 %0, %1, %2;" : "=l"(r) : "l"(a), "l"(b));
    return r;
}
__device__ __forceinline__ unsigned long long bcast2(float v) {
    unsigned long long r;
    asm("mov.b64 %0, {%1, %1};" : "=l"(r) : "f"(v));
    return r;
}
__device__ __forceinline__ unsigned long long pack2(float lo, float hi) {
    unsigned long long r;
    asm("mov.b64 %0, {%1, %2};" : "=l"(r) : "f"(lo), "f"(hi));
    return r;
}
__device__ __forceinline__ float lo2(unsigned long long v) {
    return __uint_as_float((unsigned int)v);
}
__device__ __forceinline__ float hi2(unsigned long long v) {
    return __uint_as_float((unsigned int)(v >> 32));
}
__device__ __forceinline__ float sigf(float v) {
    return __fdividef(1.0f, 1.0f + __expf(-v));
}
__device__ __forceinline__ float tanh_fast(float v) {
    return __fdividef(2.0f, 1.0f + __expf(-2.0f * v)) - 1.0f;
}

// Generation-counter grid barrier (all NBLK blocks participate)
__device__ __forceinline__ void gsync() {
    __syncthreads();
    if (threadIdx.x == 0) {
        volatile unsigned int* genp = &g_gen;
        unsigned int g = *genp;
        __threadfence();
        if (atomicAdd(&g_cnt, 1u) == NBLK - 1u) {
            atomicExch(&g_cnt, 0u);
            __threadfence();
            *genp = g + 1u;
        } else {
            while (*genp == g) { }
        }
    }
    __syncthreads();
}

// ---------- main persistent kernel ----------
extern "C" __global__ void __launch_bounds__(THREADS, 2)
lstm_persist(const float* __restrict__ x, const float* __restrict__ a,
             const float* __restrict__ y,
             const float* __restrict__ W_ih, const float* __restrict__ W_hh,
             const float* __restrict__ b_ih, const float* __restrict__ b_hh,
             const float* __restrict__ W_eta, const float* __restrict__ b_eta,
             const float* __restrict__ W_xi,  const float* __restrict__ b_xi,
             const float* __restrict__ W_zeta, const float* __restrict__ b_zeta,
             float* __restrict__ out) {
    __shared__ __align__(16) float sW[HID * GROWS];          // [k][8] = 16 KB
    __shared__ float sWx[GROWS], sWa[GROWS], sWy[GROWS], sB[GROWS];
    // Reduction buffer, transposed [p][b2] -> conflict-free STS/LDS.64
    __shared__ unsigned long long sred[GROWS * 128];         // 8 KB

    const int tid = threadIdx.x;
    const int b2  = tid & 127;       // batch pair index: batches 2*b2, 2*b2+1
    const int kh  = tid >> 7;        // k-half (warp-aligned: warps 0-3 / 4-7)
    const int bid = blockIdx.x;
    const int j0  = bid * UPB;       // first hidden unit owned by this block

    // Load this block's W_hh slice into smem, transposed to [k][local_row].
    // local row l = u*4 + g  ->  global gate row = g*HID + j0 + u
    for (int idx = tid; idx < HID * GROWS; idx += THREADS) {
        int k = idx >> 3, l = idx & 7;
        int u = l >> 2,  g = l & 3;
        int row = g * HID + j0 + u;
        sW[k * GROWS + l] = W_hh[row * HID + k];
    }
    if (tid < GROWS) {
        int u = tid >> 2, g = tid & 3;
        int row = g * HID + j0 + u;
        sWx[tid] = W_ih[row * 3 + 0];
        sWa[tid] = W_ih[row * 3 + 1];
        sWy[tid] = W_ih[row * 3 + 2];
        sB[tid]  = b_ih[row] + b_hh[row];
    }

    // Zero h state; cell state for the 2 owned units x 2 batches in registers.
    float c[2][UPB];
    #pragma unroll
    for (int u = 0; u < UPB; u++) { c[0][u] = 0.0f; c[1][u] = 0.0f; }
    if (kh == 0) {
        #pragma unroll
        for (int u = 0; u < UPB; u++)
            __stcg(reinterpret_cast<float2*>(&g_h[0][(j0 + u) * BATCH + 2 * b2]),
                   make_float2(0.0f, 0.0f));
    }
    gsync();

    const float* sWk = sW + kh * KHALF * GROWS;   // this half's weight base

    int cur = 0;
    for (int s = 0; s < T_STEPS; s++) {
        const int t = T_STEPS - 1 - s;   // reversed sequence

        // acc[0..3]: batch 2*b2 gate pairs; acc[4..7]: batch 2*b2+1.
        unsigned long long acc[8];
        if (kh == 0) {
            const float2 xv = __ldg(reinterpret_cast<const float2*>(&x[t * BATCH + 2 * b2]));
            const float2 av = __ldg(reinterpret_cast<const float2*>(&a[t * BATCH + 2 * b2]));
            const float2 yv = __ldg(reinterpret_cast<const float2*>(&y[t * BATCH + 2 * b2]));
            #pragma unroll
            for (int p = 0; p < 4; p++) {
                float wx0 = sWx[2*p], wx1 = sWx[2*p+1];
                float wa0 = sWa[2*p], wa1 = sWa[2*p+1];
                float wy0 = sWy[2*p], wy1 = sWy[2*p+1];
                float bb0 = sB[2*p],  bb1 = sB[2*p+1];
                acc[p] = pack2(
                    fmaf(wx0, xv.x, fmaf(wa0, av.x, fmaf(wy0, yv.x, bb0))),
                    fmaf(wx1, xv.x, fmaf(wa1, av.x, fmaf(wy1, yv.x, bb1))));
                acc[4 + p] = pack2(
                    fmaf(wx0, xv.y, fmaf(wa0, av.y, fmaf(wy0, yv.y, bb0))),
                    fmaf(wx1, xv.y, fmaf(wa1, av.y, fmaf(wy1, yv.y, bb1))));
            }
        } else {
            #pragma unroll
            for (int p = 0; p < 8; p++) acc[p] = 0ull;
        }

        // h slice: k in [kh*KHALF, kh*KHALF + KHALF). h[k][b]: float2 idx k*128 + b2.
        const float2* hbase =
            reinterpret_cast<const float2*>(g_h[cur]) + kh * KHALF * 128 + b2;

        float2 hbuf[4];
        #pragma unroll
        for (int i = 0; i < 4; i++) hbuf[i] = __ldcg(hbase + i * 128);

        for (int kb = 0; kb < KHALF; kb += 4) {
            #pragma unroll
            for (int j = 0; j < 4; j++) {
                float2 hv = hbuf[j];
                int ni = kb + 4 + j;
                hbuf[j] = (ni < KHALF) ? __ldcg(hbase + ni * 128)
                                       : make_float2(0.0f, 0.0f);

                const ulonglong2* wr =
                    reinterpret_cast<const ulonglong2*>(sWk + (kb + j) * GROWS);
                ulonglong2 w0 = wr[0], w1 = wr[1];
                unsigned long long ha = bcast2(hv.x);
                unsigned long long hb = bcast2(hv.y);
                ffma2(acc[0], ha, w0.x); ffma2(acc[1], ha, w0.y);
                ffma2(acc[2], ha, w1.x); ffma2(acc[3], ha, w1.y);
                ffma2(acc[4], hb, w0.x); ffma2(acc[5], hb, w0.y);
                ffma2(acc[6], hb, w1.x); ffma2(acc[7], hb, w1.y);
            }
        }

        // Cross-half reduction through smem (transposed layout, conflict-free).
        if (kh == 1) {
            #pragma unroll
            for (int p = 0; p < 8; p++) sred[p * 128 + b2] = acc[p];
        }
        __syncthreads();

        if (kh == 0) {
            #pragma unroll
            for (int p = 0; p < 8; p++)
                acc[p] = addf32x2(acc[p], sred[p * 128 + b2]);

            // Gates + state update for 2 owned units x 2 batches.
            float h0[UPB], h1[UPB];
            #pragma unroll
            for (int u = 0; u < UPB; u++) {
                // pair (2u) = (i, f), pair (2u+1) = (g, o)
                float cn0 = sigf(hi2(acc[2*u])) * c[0][u]
                          + sigf(lo2(acc[2*u])) * tanh_fast(lo2(acc[2*u+1]));
                h0[u] = sigf(hi2(acc[2*u+1])) * tanh_fast(cn0);
                c[0][u] = cn0;
                float cn1 = sigf(hi2(acc[4+2*u])) * c[1][u]
                          + sigf(lo2(acc[4+2*u])) * tanh_fast(lo2(acc[4+2*u+1]));
                h1[u] = sigf(hi2(acc[4+2*u+1])) * tanh_fast(cn1);
                c[1][u] = cn1;
            }
            float* hout = g_h[cur ^ 1];
            #pragma unroll
            for (int u = 0; u < UPB; u++)
                __stcg(reinterpret_cast<float2*>(&hout[(j0 + u) * BATCH + 2 * b2]),
                       make_float2(h0[u], h1[u]));
        }
        gsync();
        cur ^= 1;
    }

    const float* hf = g_h[cur];   // final hidden state [k][b]
    const int b = tid;            // one batch per thread for head phases

    // ---- Phase A: zx columns (blocks 0..63), ze logits (blocks 64..79) ----
    if (bid < 64) {
        const int m = bid;
        float acc = b_xi[m];
        const float* wm = W_xi + m * HID;
        #pragma unroll 8
        for (int k = 0; k < HID; k++)
            acc = fmaf(__ldcg(hf + k * BATCH + b), __ldg(&wm[k]), acc);
        out[b * 64 + m] = acc;                  // zx at offset 0: [B][64]
        __stcg(&g_zxT[m * BATCH + b], acc);
    } else if (bid < 80) {
        const int e = bid - 64;
        float acc = b_eta[e];
        const float* we = W_eta + e * HID;
        #pragma unroll 8
        for (int k = 0; k < HID; k++)
            acc = fmaf(__ldcg(hf + k * BATCH + b), __ldg(&we[k]), acc);
        __stcg(&g_zeT[e * BATCH + b], acc);
    }
    gsync();

    // ---- Phase B: zy columns (blocks 0..63), ze softmax (block 64) ----
    if (bid < 64) {
        const int m = bid;
        float acc = b_zeta[m];
        const float* wz = W_zeta + m * (HID + 64);
        #pragma unroll 8
        for (int k = 0; k < HID; k++)
            acc = fmaf(__ldcg(hf + k * BATCH + b), __ldg(&wz[k]), acc);
        #pragma unroll
        for (int j = 0; j < 64; j++)
            acc = fmaf(__ldcg(&g_zxT[j * BATCH + b]), __ldg(&wz[HID + j]), acc);
        out[16384 + b * 64 + m] = acc;          // zy at offset 16384: [B][64]
    } else if (bid == 80) {
        float l[16];
        float mx = -1e30f;
        #pragma unroll
        for (int e = 0; e < 16; e++) {
            l[e] = __ldcg(&g_zeT[e * BATCH + b]);
            mx = fmaxf(mx, l[e]);
        }
        float ssum = 0.0f;
        #pragma unroll
        for (int e = 0; e < 16; e++) { l[e] = __expf(l[e] - mx); ssum += l[e]; }
        float inv = __fdividef(1.0f, ssum);
        #pragma unroll
        for (int e = 0; e < 16; e++)
            out[32768 + b * 16 + e] = l[e] * inv;   // ze at offset 32768: [B][16]
    }
}

extern "C" void kernel_launch(void* const* d_in, const int* in_sizes, int n_in,
                              void* d_out, int out_size) {
    const float* x      = (const float*)d_in[0];
    const float* a      = (const float*)d_in[1];
    const float* y      = (const float*)d_in[2];
    const float* W_ih   = (const float*)d_in[3];
    const float* W_hh   = (const float*)d_in[4];
    const float* b_ih   = (const float*)d_in[5];
    const float* b_hh   = (const float*)d_in[6];
    const float* W_eta  = (const float*)d_in[7];
    const float* b_eta  = (const float*)d_in[8];
    const float* W_xi   = (const float*)d_in[9];
    const float* b_xi   = (const float*)d_in[10];
    const float* W_zeta = (const float*)d_in[11];
    const float* b_zeta = (const float*)d_in[12];

    lstm_persist<<<NBLK, THREADS>>>(x, a, y, W_ih, W_hh, b_ih, b_hh,
                                    W_eta, b_eta, W_xi, b_xi, W_zeta, b_zeta,
                                    (float*)d_out);
}

// round 6
// speedup vs baseline: 1.0763x; 1.0763x over previous
#include <cuda_runtime.h>

#define T_STEPS 1024
#define BATCH   256
#define HID     512
#define NBLK    128
#define THREADS 512
#define KS      4                 // k-split factor (warp-aligned quarters)
#define KQ      (HID / KS)        // 128 k per quarter
#define UPB     4                 // hidden units per block
#define GROWS   16                // gate rows per block (4 units x 4 gates)
#define NLEAF   16                // barrier leaves (8 blocks each)

// Persistent device state (allocation-free scratch)
__device__ float g_h[2][HID * BATCH];   // h[k][b]
__device__ float g_zxT[64 * BATCH];     // zx transposed [col][b]
__device__ float g_zeT[16 * BATCH];     // ze logits transposed [col][b]
__device__ unsigned int g_leaf[NLEAF];  // zero-initialized
__device__ unsigned int g_master;       // zero-initialized
__device__ unsigned int g_gen;          // zero-initialized

// ---------- helpers ----------
__device__ __forceinline__ void ffma2(unsigned long long& d,
                                      unsigned long long a,
                                      unsigned long long b) {
    asm("fma.rn.f32x2 %0, %1, %2, %0;" : "+l"(d) : "l"(a), "l"(b));
}
__device__ __forceinline__ unsigned long long addf32x2(unsigned long long a,
                                                       unsigned long long b) {
    unsigned long long r;
    asm("add.rn.f32x2 %0, %1, %2;" : "=l"(r) : "l"(a), "l"(b));
    return r;
}
__device__ __forceinline__ unsigned long long bcast2(float v) {
    unsigned long long r;
    asm("mov.b64 %0, {%1, %1};" : "=l"(r) : "f"(v));
    return r;
}
__device__ __forceinline__ unsigned long long pack2(float lo, float hi) {
    unsigned long long r;
    asm("mov.b64 %0, {%1, %2};" : "=l"(r) : "f"(lo), "f"(hi));
    return r;
}
__device__ __forceinline__ float lo2(unsigned long long v) {
    return __uint_as_float((unsigned int)v);
}
__device__ __forceinline__ float hi2(unsigned long long v) {
    return __uint_as_float((unsigned int)(v >> 32));
}
__device__ __forceinline__ float sigf(float v) {
    return __fdividef(1.0f, 1.0f + __expf(-v));
}
__device__ __forceinline__ float tanh_fast(float v) {
    return __fdividef(2.0f, 1.0f + __expf(-2.0f * v)) - 1.0f;
}

// Hierarchical generation-counter grid barrier (128 blocks: 16 leaves x 8)
__device__ __forceinline__ void gsync(int bid) {
    __syncthreads();
    if (threadIdx.x == 0) {
        volatile unsigned int* genp = &g_gen;
        unsigned int g = *genp;
        __threadfence();
        bool release = false;
        if (atomicAdd(&g_leaf[bid & (NLEAF - 1)], 1u) == (NBLK / NLEAF) - 1u) {
            if (atomicAdd(&g_master, 1u) == NLEAF - 1u) {
                // Final arriver: reset counters, then publish new generation.
                #pragma unroll
                for (int i = 0; i < NLEAF; i++) g_leaf[i] = 0u;
                g_master = 0u;
                __threadfence();
                *genp = g + 1u;
                release = true;
            }
        }
        if (!release) {
            while (*genp == g) { }
        }
    }
    __syncthreads();
}

// ---------- main persistent kernel ----------
extern "C" __global__ void __launch_bounds__(THREADS, 1)
lstm_persist(const float* __restrict__ x, const float* __restrict__ a,
             const float* __restrict__ y,
             const float* __restrict__ W_ih, const float* __restrict__ W_hh,
             const float* __restrict__ b_ih, const float* __restrict__ b_hh,
             const float* __restrict__ W_eta, const float* __restrict__ b_eta,
             const float* __restrict__ W_xi,  const float* __restrict__ b_xi,
             const float* __restrict__ W_zeta, const float* __restrict__ b_zeta,
             float* __restrict__ out) {
    __shared__ __align__(16) float sW[HID * GROWS];          // [k][16] = 32 KB
    __shared__ float sWx[GROWS], sWa[GROWS], sWy[GROWS], sB[GROWS];
    // Two reduction buffers [p][b2], conflict-free STS/LDS.64 (2 x 16 KB)
    __shared__ unsigned long long sred[2][GROWS * 128];

    const int tid = threadIdx.x;
    const int b2  = tid & 127;       // batch pair index: batches 2*b2, 2*b2+1
    const int kq  = tid >> 7;        // k-quarter (warp-aligned: 4 warps each)
    const int bid = blockIdx.x;
    const int j0  = bid * UPB;       // first hidden unit owned by this block

    // Load this block's W_hh slice into smem, transposed to [k][local_row].
    // local row l = u*4 + g  ->  global gate row = g*HID + j0 + u
    for (int idx = tid; idx < HID * GROWS; idx += THREADS) {
        int k = idx >> 4, l = idx & 15;
        int u = l >> 2,  g = l & 3;
        int row = g * HID + j0 + u;
        sW[k * GROWS + l] = W_hh[row * HID + k];
    }
    if (tid < GROWS) {
        int u = tid >> 2, g = tid & 3;
        int row = g * HID + j0 + u;
        sWx[tid] = W_ih[row * 3 + 0];
        sWa[tid] = W_ih[row * 3 + 1];
        sWy[tid] = W_ih[row * 3 + 2];
        sB[tid]  = b_ih[row] + b_hh[row];
    }

    // Zero h state; cell state for 4 owned units x 2 batches in registers (kq 0).
    float c[2][UPB];
    #pragma unroll
    for (int u = 0; u < UPB; u++) { c[0][u] = 0.0f; c[1][u] = 0.0f; }
    if (kq == 0) {
        #pragma unroll
        for (int u = 0; u < UPB; u++)
            __stcg(reinterpret_cast<float2*>(&g_h[0][(j0 + u) * BATCH + 2 * b2]),
                   make_float2(0.0f, 0.0f));
    }

    // Preload step-0 inputs (t = T-1).
    float2 xv = make_float2(0.f, 0.f), av = xv, yv = xv;
    if (kq == 0) {
        xv = __ldg(reinterpret_cast<const float2*>(&x[(T_STEPS - 1) * BATCH + 2 * b2]));
        av = __ldg(reinterpret_cast<const float2*>(&a[(T_STEPS - 1) * BATCH + 2 * b2]));
        yv = __ldg(reinterpret_cast<const float2*>(&y[(T_STEPS - 1) * BATCH + 2 * b2]));
    }
    gsync(bid);

    const float* sWk = sW + kq * KQ * GROWS;   // this quarter's weight base

    int cur = 0;
    for (int s = 0; s < T_STEPS; s++) {
        // acc[0..7]: batch 2*b2 gate pairs; acc[8..15]: batch 2*b2+1.
        unsigned long long acc[16];
        if (kq == 0) {
            #pragma unroll
            for (int p = 0; p < 8; p++) {
                float wx0 = sWx[2*p], wx1 = sWx[2*p+1];
                float wa0 = sWa[2*p], wa1 = sWa[2*p+1];
                float wy0 = sWy[2*p], wy1 = sWy[2*p+1];
                float bb0 = sB[2*p],  bb1 = sB[2*p+1];
                acc[p] = pack2(
                    fmaf(wx0, xv.x, fmaf(wa0, av.x, fmaf(wy0, yv.x, bb0))),
                    fmaf(wx1, xv.x, fmaf(wa1, av.x, fmaf(wy1, yv.x, bb1))));
                acc[8 + p] = pack2(
                    fmaf(wx0, xv.y, fmaf(wa0, av.y, fmaf(wy0, yv.y, bb0))),
                    fmaf(wx1, xv.y, fmaf(wa1, av.y, fmaf(wy1, yv.y, bb1))));
            }
            // Prefetch next step's inputs during the k-loop.
            int tn = (s + 1 < T_STEPS) ? (T_STEPS - 2 - s) : 0;
            xv = __ldg(reinterpret_cast<const float2*>(&x[tn * BATCH + 2 * b2]));
            av = __ldg(reinterpret_cast<const float2*>(&a[tn * BATCH + 2 * b2]));
            yv = __ldg(reinterpret_cast<const float2*>(&y[tn * BATCH + 2 * b2]));
        } else {
            #pragma unroll
            for (int p = 0; p < 16; p++) acc[p] = 0ull;
        }

        // h slice: k in [kq*KQ, kq*KQ + KQ). h[k][b]: float2 index k*128 + b2.
        const float2* hbase =
            reinterpret_cast<const float2*>(g_h[cur]) + kq * KQ * 128 + b2;

        float2 hbuf[2];
        hbuf[0] = __ldcg(hbase);
        hbuf[1] = __ldcg(hbase + 128);

        for (int kb = 0; kb < KQ; kb += 2) {
            #pragma unroll
            for (int j = 0; j < 2; j++) {
                float2 hv = hbuf[j];
                int ni = kb + 2 + j;
                hbuf[j] = (ni < KQ) ? __ldcg(hbase + ni * 128)
                                    : make_float2(0.0f, 0.0f);

                const ulonglong2* wr =
                    reinterpret_cast<const ulonglong2*>(sWk + (kb + j) * GROWS);
                ulonglong2 w0 = wr[0], w1 = wr[1], w2 = wr[2], w3 = wr[3];
                unsigned long long ha = bcast2(hv.x);
                unsigned long long hb = bcast2(hv.y);
                ffma2(acc[0], ha, w0.x); ffma2(acc[1], ha, w0.y);
                ffma2(acc[2], ha, w1.x); ffma2(acc[3], ha, w1.y);
                ffma2(acc[4], ha, w2.x); ffma2(acc[5], ha, w2.y);
                ffma2(acc[6], ha, w3.x); ffma2(acc[7], ha, w3.y);
                ffma2(acc[8],  hb, w0.x); ffma2(acc[9],  hb, w0.y);
                ffma2(acc[10], hb, w1.x); ffma2(acc[11], hb, w1.y);
                ffma2(acc[12], hb, w2.x); ffma2(acc[13], hb, w2.y);
                ffma2(acc[14], hb, w3.x); ffma2(acc[15], hb, w3.y);
            }
        }

        // Tree reduction across the 4 quarters.
        if (kq >= 2) {
            #pragma unroll
            for (int p = 0; p < 16; p++) sred[kq - 2][p * 128 + b2] = acc[p];
        }
        __syncthreads();
        if (kq == 1) {
            #pragma unroll
            for (int p = 0; p < 16; p++) {
                // read kq3's partial, fold in, write back to same slot (same thread)
                acc[p] = addf32x2(acc[p], sred[1][p * 128 + b2]);
                sred[1][p * 128 + b2] = acc[p];
            }
        } else if (kq == 0) {
            #pragma unroll
            for (int p = 0; p < 16; p++)
                acc[p] = addf32x2(acc[p], sred[0][p * 128 + b2]);
        }
        __syncthreads();

        if (kq == 0) {
            #pragma unroll
            for (int p = 0; p < 16; p++)
                acc[p] = addf32x2(acc[p], sred[1][p * 128 + b2]);

            // Gates + state update for 4 owned units x 2 batches.
            float h0[UPB], h1[UPB];
            #pragma unroll
            for (int u = 0; u < UPB; u++) {
                // pair (2u) = (i, f), pair (2u+1) = (g, o)
                float cn0 = sigf(hi2(acc[2*u])) * c[0][u]
                          + sigf(lo2(acc[2*u])) * tanh_fast(lo2(acc[2*u+1]));
                h0[u] = sigf(hi2(acc[2*u+1])) * tanh_fast(cn0);
                c[0][u] = cn0;
                float cn1 = sigf(hi2(acc[8+2*u])) * c[1][u]
                          + sigf(lo2(acc[8+2*u])) * tanh_fast(lo2(acc[8+2*u+1]));
                h1[u] = sigf(hi2(acc[8+2*u+1])) * tanh_fast(cn1);
                c[1][u] = cn1;
            }
            float* hout = g_h[cur ^ 1];
            #pragma unroll
            for (int u = 0; u < UPB; u++)
                __stcg(reinterpret_cast<float2*>(&hout[(j0 + u) * BATCH + 2 * b2]),
                       make_float2(h0[u], h1[u]));
        }
        gsync(bid);
        cur ^= 1;
    }

    const float* hf = g_h[cur];   // final hidden state [k][b]
    const int b = tid;            // one batch per thread for head phases

    // ---- Phase A: zx columns (blocks 0..63), ze logits (blocks 64..79) ----
    if (b < BATCH) {
        if (bid < 64) {
            const int m = bid;
            float acc = b_xi[m];
            const float* wm = W_xi + m * HID;
            #pragma unroll 8
            for (int k = 0; k < HID; k++)
                acc = fmaf(__ldcg(hf + k * BATCH + b), __ldg(&wm[k]), acc);
            out[b * 64 + m] = acc;                  // zx at offset 0: [B][64]
            __stcg(&g_zxT[m * BATCH + b], acc);
        } else if (bid < 80) {
            const int e = bid - 64;
            float acc = b_eta[e];
            const float* we = W_eta + e * HID;
            #pragma unroll 8
            for (int k = 0; k < HID; k++)
                acc = fmaf(__ldcg(hf + k * BATCH + b), __ldg(&we[k]), acc);
            __stcg(&g_zeT[e * BATCH + b], acc);
        }
    }
    gsync(bid);

    // ---- Phase B: zy columns (blocks 0..63), ze softmax (block 64) ----
    if (b < BATCH) {
        if (bid < 64) {
            const int m = bid;
            float acc = b_zeta[m];
            const float* wz = W_zeta + m * (HID + 64);
            #pragma unroll 8
            for (int k = 0; k < HID; k++)
                acc = fmaf(__ldcg(hf + k * BATCH + b), __ldg(&wz[k]), acc);
            #pragma unroll
            for (int j = 0; j < 64; j++)
                acc = fmaf(__ldcg(&g_zxT[j * BATCH + b]), __ldg(&wz[HID + j]), acc);
            out[16384 + b * 64 + m] = acc;          // zy at offset 16384: [B][64]
        } else if (bid == 64) {
            float l[16];
            float mx = -1e30f;
            #pragma unroll
            for (int e = 0; e < 16; e++) {
                l[e] = __ldcg(&g_zeT[e * BATCH + b]);
                mx = fmaxf(mx, l[e]);
            }
            float ssum = 0.0f;
            #pragma unroll
            for (int e = 0; e < 16; e++) { l[e] = __expf(l[e] - mx); ssum += l[e]; }
            float inv = __fdividef(1.0f, ssum);
            #pragma unroll
            for (int e = 0; e < 16; e++)
                out[32768 + b * 16 + e] = l[e] * inv;   // ze at offset 32768: [B][16]
        }
    }
}

extern "C" void kernel_launch(void* const* d_in, const int* in_sizes, int n_in,
                              void* d_out, int out_size) {
    const float* x      = (const float*)d_in[0];
    const float* a      = (const float*)d_in[1];
    const float* y      = (const float*)d_in[2];
    const float* W_ih   = (const float*)d_in[3];
    const float* W_hh   = (const float*)d_in[4];
    const float* b_ih   = (const float*)d_in[5];
    const float* b_hh   = (const float*)d_in[6];
    const float* W_eta  = (const float*)d_in[7];
    const float* b_eta  = (const float*)d_in[8];
    const float* W_xi   = (const float*)d_in[9];
    const float* b_xi   = (const float*)d_in[10];
    const float* W_zeta = (const float*)d_in[11];
    const float* b_zeta = (const float*)d_in[12];

    lstm_persist<<<NBLK, THREADS>>>(x, a, y, W_ih, W_hh, b_ih, b_hh,
                                    W_eta, b_eta, W_xi, b_xi, W_zeta, b_zeta,
                                    (float*)d_out);
}

// round 8
// speedup vs baseline: 1.5875x; 1.4749x over previous
#include <cuda_runtime.h>
#include <cuda_bf16.h>

#define T_STEPS 1024
#define BATCH   256
#define HID     512
#define NBLK    128
#define THREADS 512
#define NLEAF   16

// 2D tiling: 4 batch-slices x 32 unit-slices
#define MB       64      // batches per block
#define NG       64      // gate columns per block (16 units x 4 gates)
#define UNITS    16

// smem layout (bytes)
#define WPITCH    72                          // bf16 per k-row (64 + 8 pad) = 144 B
#define WBYTES    (HID * WPITCH * 2)          // 73728 per W matrix
#define OFF_WHI   0
#define OFF_WLO   WBYTES                      // 73728
#define OFF_A     (2 * WBYTES)                // 147456
#define ABUF_BYTES (MB * 272)                 // 64 rows x 272B = 17408
#define OFF_P     (OFF_A + 4 * ABUF_BYTES)    // 217088
#define SMEM_TOTAL (OFF_P + 1024)             // 218112

// Persistent device state
__device__ __nv_bfloat16 g_hhi[2][BATCH * HID];
__device__ __nv_bfloat16 g_hlo[2][BATCH * HID];
__device__ float g_zxT[64 * BATCH];
__device__ float g_zeT[16 * BATCH];
__device__ unsigned int g_leaf[NLEAF];
__device__ unsigned int g_master;
__device__ unsigned int g_gen;

// ---------- helpers ----------
__device__ __forceinline__ unsigned s2u(const void* p) {
    unsigned r;
    asm("{ .reg .u64 t; cvta.to.shared.u64 t, %1; cvt.u32.u64 %0, t; }"
        : "=r"(r) : "l"(p));
    return r;
}

__device__ __forceinline__ void mma16816(float* d, const unsigned* a, const unsigned* b) {
    asm volatile(
        "mma.sync.aligned.m16n8k16.row.col.f32.bf16.bf16.f32 "
        "{%0,%1,%2,%3}, {%4,%5,%6,%7}, {%8,%9}, {%0,%1,%2,%3};"
        : "+f"(d[0]), "+f"(d[1]), "+f"(d[2]), "+f"(d[3])
        : "r"(a[0]), "r"(a[1]), "r"(a[2]), "r"(a[3]), "r"(b[0]), "r"(b[1]));
}

__device__ __forceinline__ void ldsm_x4(unsigned* r, unsigned addr) {
    asm volatile("ldmatrix.sync.aligned.m8n8.x4.shared.b16 {%0,%1,%2,%3}, [%4];"
                 : "=r"(r[0]), "=r"(r[1]), "=r"(r[2]), "=r"(r[3]) : "r"(addr));
}
__device__ __forceinline__ void ldsm_x2t(unsigned* r, unsigned addr) {
    asm volatile("ldmatrix.sync.aligned.m8n8.x2.trans.shared.b16 {%0,%1}, [%2];"
                 : "=r"(r[0]), "=r"(r[1]) : "r"(addr));
}

__device__ __forceinline__ float sigf(float v) {
    return __fdividef(1.0f, 1.0f + __expf(-v));
}
__device__ __forceinline__ float tanh_fast(float v) {
    return __fdividef(2.0f, 1.0f + __expf(-2.0f * v)) - 1.0f;
}

// Hierarchical generation-counter grid barrier (128 blocks: 16 leaves x 8)
__device__ __forceinline__ void gsync(int bid) {
    __syncthreads();
    if (threadIdx.x == 0) {
        volatile unsigned int* genp = &g_gen;
        unsigned int g = *genp;
        __threadfence();
        bool release = false;
        if (atomicAdd(&g_leaf[bid & (NLEAF - 1)], 1u) == (NBLK / NLEAF) - 1u) {
            if (atomicAdd(&g_master, 1u) == NLEAF - 1u) {
                #pragma unroll
                for (int i = 0; i < NLEAF; i++) g_leaf[i] = 0u;
                g_master = 0u;
                __threadfence();
                *genp = g + 1u;
                release = true;
            }
        }
        if (!release) {
            while (*genp == g) { }
        }
    }
    __syncthreads();
}

// Load A chunk (hi & lo) from global into registers
__device__ __forceinline__ void lda_g(const uint4* Ghi, const uint4* Glo,
                                      int mi, int ck, int tid,
                                      uint4* ph, uint4* pl) {
    #pragma unroll
    for (int i2 = 0; i2 < 2; i2++) {
        int sl = tid + i2 * THREADS;
        int r = sl >> 4, c = sl & 15;
        int gi = (mi * MB + r) * 64 + ck * 16 + c;   // 64 uint4 per h row
        ph[i2] = __ldcg(Ghi + gi);
        pl[i2] = __ldcg(Glo + gi);
    }
}
__device__ __forceinline__ void sta_s(char* smem, int buf, int tid,
                                      const uint4* ph, const uint4* pl) {
    uint4* dh = (uint4*)(smem + OFF_A + (buf * 2 + 0) * ABUF_BYTES);
    uint4* dl = (uint4*)(smem + OFF_A + (buf * 2 + 1) * ABUF_BYTES);
    #pragma unroll
    for (int i2 = 0; i2 < 2; i2++) {
        int sl = tid + i2 * THREADS;
        int r = sl >> 4, c = sl & 15;
        dh[r * 17 + c] = ph[i2];   // 272B row = 17 uint4
        dl[r * 17 + c] = pl[i2];
    }
}

// ---------- main persistent kernel ----------
extern "C" __global__ void __launch_bounds__(THREADS, 1)
lstm_persist(const float* __restrict__ x, const float* __restrict__ a,
             const float* __restrict__ y,
             const float* __restrict__ W_ih, const float* __restrict__ W_hh,
             const float* __restrict__ b_ih, const float* __restrict__ b_hh,
             const float* __restrict__ W_eta, const float* __restrict__ b_eta,
             const float* __restrict__ W_xi,  const float* __restrict__ b_xi,
             const float* __restrict__ W_zeta, const float* __restrict__ b_zeta,
             float* __restrict__ out) {
    extern __shared__ char smem[];
    __nv_bfloat16* sWhi = (__nv_bfloat16*)(smem + OFF_WHI);
    __nv_bfloat16* sWlo = (__nv_bfloat16*)(smem + OFF_WLO);
    float* swx = (float*)(smem + OFF_P);
    float* swa = swx + 64;
    float* swy = swx + 128;
    float* sbb = swx + 192;
    const unsigned sb = s2u(smem);

    const int tid  = threadIdx.x;
    const int lane = tid & 31;
    const int w    = tid >> 5;       // 16 warps
    const int bid  = blockIdx.x;
    const int mi   = bid >> 5;       // batch slice 0..3
    const int ni   = bid & 31;       // unit slice 0..31
    const int wm   = w & 3;          // m-tile: rows 16*wm .. +15
    const int wn   = w >> 2;         // n-group: cols 16*wn (two 8-wide tiles)

    // ---- W tile into smem, K-MAJOR: sW[k][j], pitch WPITCH bf16 ----
    // ldmatrix.x2.trans from k-major rows yields the correct mma B fragment.
    for (int idx = tid; idx < NG * HID; idx += THREADS) {
        int j = idx >> 9, k = idx & 511;                 // iter j, thread k (coalesced read)
        int row = (j & 3) * HID + ni * UNITS + (j >> 2); // gate row in W_hh
        float v = W_hh[row * HID + k];
        __nv_bfloat16 hi = __float2bfloat16(v);
        sWhi[k * WPITCH + j] = hi;
        sWlo[k * WPITCH + j] = __float2bfloat16(v - __bfloat162float(hi));
    }
    if (tid < NG) {
        int row = (tid & 3) * HID + ni * UNITS + (tid >> 2);
        swx[tid] = W_ih[row * 3 + 0];
        swa[tid] = W_ih[row * 3 + 1];
        swy[tid] = W_ih[row * 3 + 2];
        sbb[tid] = b_ih[row] + b_hh[row];
    }

    // ---- zero our slice of h (buffer 0) ----
    for (int e = tid; e < MB * UNITS; e += THREADS) {
        int bl = e >> 4, ku = e & 15;
        int gi = (mi * MB + bl) * HID + ni * UNITS + ku;
        g_hhi[0][gi] = __float2bfloat16(0.0f);
        g_hlo[0][gi] = __float2bfloat16(0.0f);
    }
    gsync(bid);

    // epilogue ownership
    const bool act = ((lane & 1) == 0);
    const int qr = lane >> 2;
    const int r0 = 16 * wm + qr;            // local batch rows
    const int b0g = mi * MB + r0;
    const int b1g = b0g + 8;
    float cst[2][2] = {{0.f, 0.f}, {0.f, 0.f}};

    // ldmatrix address components (constant per thread)
    const unsigned arow  = (unsigned)((16 * wm + (lane & 15)) * 272);
    const unsigned acol  = (unsigned)((lane >> 4) * 16);
    // B (k-major): lanes 0-7 -> k-rows 0-7, lanes 8-15 -> k-rows 8-15; col = n
    const unsigned bbase = (unsigned)(((lane & 7) + ((lane >> 3) & 1) * 8) * (WPITCH * 2)
                                      + (16 * wn) * 2);

    int cur = 0;
    for (int s = 0; s < T_STEPS; s++) {
        const int t = T_STEPS - 1 - s;

        // inputs for this step's epilogue (rows r0, r1)
        float x0 = __ldg(&x[t * BATCH + b0g]);
        float a0 = __ldg(&a[t * BATCH + b0g]);
        float y0 = __ldg(&y[t * BATCH + b0g]);
        float x1 = __ldg(&x[t * BATCH + b1g]);
        float a1 = __ldg(&a[t * BATCH + b1g]);
        float y1 = __ldg(&y[t * BATCH + b1g]);

        const uint4* Ghi = (const uint4*)(g_hhi[cur]);
        const uint4* Glo = (const uint4*)(g_hlo[cur]);

        // chunk 0 -> smem buf 0
        {
            uint4 ph[2], pl[2];
            lda_g(Ghi, Glo, mi, 0, tid, ph, pl);
            sta_s(smem, 0, tid, ph, pl);
        }
        __syncthreads();

        float acc[2][4] = {{0.f, 0.f, 0.f, 0.f}, {0.f, 0.f, 0.f, 0.f}};

        for (int ck = 0; ck < 4; ck++) {
            uint4 ph[2], pl[2];
            const bool more = (ck < 3);
            if (more) lda_g(Ghi, Glo, mi, ck + 1, tid, ph, pl);

            const unsigned Ahb = sb + OFF_A + ((ck & 1) * 2 + 0) * ABUF_BYTES;
            const unsigned Alb = sb + OFF_A + ((ck & 1) * 2 + 1) * ABUF_BYTES;

            #pragma unroll
            for (int kt = 0; kt < 8; kt++) {
                unsigned ahi[4], alo[4];
                unsigned aoff = arow + (unsigned)(kt * 32) + acol;
                ldsm_x4(ahi, Ahb + aoff);
                ldsm_x4(alo, Alb + aoff);
                const unsigned kb = bbase + (unsigned)((ck * 128 + kt * 16) * (WPITCH * 2));
                #pragma unroll
                for (int nt = 0; nt < 2; nt++) {
                    unsigned boff = kb + (unsigned)(nt * 16);
                    unsigned bhi[2], blo[2];
                    ldsm_x2t(bhi, sb + OFF_WHI + boff);
                    ldsm_x2t(blo, sb + OFF_WLO + boff);
                    mma16816(acc[nt], ahi, bhi);
                    mma16816(acc[nt], ahi, blo);
                    mma16816(acc[nt], alo, bhi);
                }
            }
            __syncthreads();
            if (more) sta_s(smem, (ck + 1) & 1, tid, ph, pl);
            __syncthreads();
        }

        // ---- epilogue: xproj add, fragment exchange, gates, h store ----
        #pragma unroll
        for (int nt = 0; nt < 2; nt++) {
            int ce = 16 * wn + nt * 8 + 2 * (lane & 3);
            int co = ce + 1;
            float wxe = swx[ce], wae = swa[ce], wye = swy[ce], bbe = sbb[ce];
            float wxo = swx[co], wao = swa[co], wyo = swy[co], bbo = sbb[co];
            acc[nt][0] += fmaf(wxe, x0, fmaf(wae, a0, fmaf(wye, y0, bbe)));
            acc[nt][1] += fmaf(wxo, x0, fmaf(wao, a0, fmaf(wyo, y0, bbo)));
            acc[nt][2] += fmaf(wxe, x1, fmaf(wae, a1, fmaf(wye, y1, bbe)));
            acc[nt][3] += fmaf(wxo, x1, fmaf(wao, a1, fmaf(wyo, y1, bbo)));
        }

        float gg[2][4];
        #pragma unroll
        for (int nt = 0; nt < 2; nt++)
            #pragma unroll
            for (int i = 0; i < 4; i++)
                gg[nt][i] = __shfl_xor_sync(0xffffffffu, acc[nt][i], 1);

        if (act) {
            __nv_bfloat16* Hhi = g_hhi[cur ^ 1];
            __nv_bfloat16* Hlo = g_hlo[cur ^ 1];
            #pragma unroll
            for (int nt = 0; nt < 2; nt++) {
                int lu = 4 * wn + nt * 2 + ((lane & 3) >> 1);
                int kg = ni * UNITS + lu;
                #pragma unroll
                for (int rr = 0; rr < 2; rr++) {
                    float iv = acc[nt][2 * rr + 0];
                    float fv = acc[nt][2 * rr + 1];
                    float gv = gg[nt][2 * rr + 0];
                    float ov = gg[nt][2 * rr + 1];
                    float cn = sigf(fv) * cst[nt][rr] + sigf(iv) * tanh_fast(gv);
                    cst[nt][rr] = cn;
                    float h = sigf(ov) * tanh_fast(cn);
                    int bg = rr ? b1g : b0g;
                    __nv_bfloat16 hh = __float2bfloat16(h);
                    Hhi[bg * HID + kg] = hh;
                    Hlo[bg * HID + kg] = __float2bfloat16(h - __bfloat162float(hh));
                }
            }
        }
        gsync(bid);
        cur ^= 1;
    }

    // ---- final heads: reconstruct h = hi + lo ----
    const __nv_bfloat16* Fhi = g_hhi[cur];
    const __nv_bfloat16* Flo = g_hlo[cur];
    const int b = tid;

    // Phase A: zx columns (blocks 0..63), ze logits (blocks 64..79)
    if (b < BATCH) {
        if (bid < 64) {
            const int m = bid;
            float acc = b_xi[m];
            const float* wm_ = W_xi + m * HID;
            #pragma unroll 8
            for (int k = 0; k < HID; k++) {
                float hv = __bfloat162float(Fhi[b * HID + k]) +
                           __bfloat162float(Flo[b * HID + k]);
                acc = fmaf(hv, __ldg(&wm_[k]), acc);
            }
            out[b * 64 + m] = acc;                  // zx: [B][64] at 0
            g_zxT[m * BATCH + b] = acc;
        } else if (bid < 80) {
            const int e = bid - 64;
            float acc = b_eta[e];
            const float* we = W_eta + e * HID;
            #pragma unroll 8
            for (int k = 0; k < HID; k++) {
                float hv = __bfloat162float(Fhi[b * HID + k]) +
                           __bfloat162float(Flo[b * HID + k]);
                acc = fmaf(hv, __ldg(&we[k]), acc);
            }
            g_zeT[e * BATCH + b] = acc;
        }
    }
    gsync(bid);

    // Phase B: zy columns (blocks 0..63), ze softmax (block 64)
    if (b < BATCH) {
        if (bid < 64) {
            const int m = bid;
            float acc = b_zeta[m];
            const float* wz = W_zeta + m * (HID + 64);
            #pragma unroll 8
            for (int k = 0; k < HID; k++) {
                float hv = __bfloat162float(Fhi[b * HID + k]) +
                           __bfloat162float(Flo[b * HID + k]);
                acc = fmaf(hv, __ldg(&wz[k]), acc);
            }
            #pragma unroll
            for (int j = 0; j < 64; j++)
                acc = fmaf(g_zxT[j * BATCH + b], __ldg(&wz[HID + j]), acc);
            out[16384 + b * 64 + m] = acc;          // zy: [B][64] at 16384
        } else if (bid == 64) {
            float l[16];
            float mx = -1e30f;
            #pragma unroll
            for (int e = 0; e < 16; e++) {
                l[e] = g_zeT[e * BATCH + b];
                mx = fmaxf(mx, l[e]);
            }
            float ssum = 0.0f;
            #pragma unroll
            for (int e = 0; e < 16; e++) { l[e] = __expf(l[e] - mx); ssum += l[e]; }
            float inv = __fdividef(1.0f, ssum);
            #pragma unroll
            for (int e = 0; e < 16; e++)
                out[32768 + b * 16 + e] = l[e] * inv;   // ze: [B][16] at 32768
        }
    }
}

extern "C" void kernel_launch(void* const* d_in, const int* in_sizes, int n_in,
                              void* d_out, int out_size) {
    const float* x      = (const float*)d_in[0];
    const float* a      = (const float*)d_in[1];
    const float* y      = (const float*)d_in[2];
    const float* W_ih   = (const float*)d_in[3];
    const float* W_hh   = (const float*)d_in[4];
    const float* b_ih   = (const float*)d_in[5];
    const float* b_hh   = (const float*)d_in[6];
    const float* W_eta  = (const float*)d_in[7];
    const float* b_eta  = (const float*)d_in[8];
    const float* W_xi   = (const float*)d_in[9];
    const float* b_xi   = (const float*)d_in[10];
    const float* W_zeta = (const float*)d_in[11];
    const float* b_zeta = (const float*)d_in[12];

    cudaFuncSetAttribute(lstm_persist,
                         cudaFuncAttributeMaxDynamicSharedMemorySize, SMEM_TOTAL);
    lstm_persist<<<NBLK, THREADS, SMEM_TOTAL>>>(
        x, a, y, W_ih, W_hh, b_ih, b_hh,
        W_eta, b_eta, W_xi, b_xi, W_zeta, b_zeta,
        (float*)d_out);
}

// round 9
// speedup vs baseline: 1.6614x; 1.0466x over previous
#include <cuda_runtime.h>
#include <cuda_bf16.h>

#define T_STEPS 1024
#define BATCH   256
#define HID     512
#define NBLK    128
#define THREADS 512
#define NLEAF   16

// 2D tiling: 4 batch-slices x 32 unit-slices
#define MB       64      // batches per block
#define NG       64      // gate columns per block (16 units x 4 gates)
#define UNITS    16

// smem layout (bytes)
#define WPITCH    72                          // bf16 per k-row (64 + 8 pad) = 144 B
#define WBYTES    (HID * WPITCH * 2)          // 73728 per W matrix
#define OFF_WHI   0
#define OFF_WLO   WBYTES                      // 73728
#define OFF_A     (2 * WBYTES)                // 147456
#define ABUF_BYTES (MB * 272)                 // 64 rows x 272B = 17408
#define OFF_P     (OFF_A + 4 * ABUF_BYTES)    // 217088
#define SMEM_TOTAL (OFF_P + 1024)             // 218112

// Persistent device state
__device__ __nv_bfloat16 g_hhi[2][BATCH * HID];
__device__ __nv_bfloat16 g_hlo[2][BATCH * HID];
__device__ float g_zxT[64 * BATCH];
__device__ float g_zeT[16 * BATCH];
__device__ unsigned int g_leaf[NLEAF];
__device__ unsigned int g_master;
__device__ unsigned int g_gen;
__device__ unsigned int g_gcnt[4 * 32];   // per-group counters, 128B apart
__device__ unsigned int g_ggen[4 * 32];

// ---------- helpers ----------
__device__ __forceinline__ unsigned s2u(const void* p) {
    unsigned r;
    asm("{ .reg .u64 t; cvta.to.shared.u64 t, %1; cvt.u32.u64 %0, t; }"
        : "=r"(r) : "l"(p));
    return r;
}

__device__ __forceinline__ void mma16816(float* d, const unsigned* a, const unsigned* b) {
    asm volatile(
        "mma.sync.aligned.m16n8k16.row.col.f32.bf16.bf16.f32 "
        "{%0,%1,%2,%3}, {%4,%5,%6,%7}, {%8,%9}, {%0,%1,%2,%3};"
        : "+f"(d[0]), "+f"(d[1]), "+f"(d[2]), "+f"(d[3])
        : "r"(a[0]), "r"(a[1]), "r"(a[2]), "r"(a[3]), "r"(b[0]), "r"(b[1]));
}

__device__ __forceinline__ void ldsm_x4(unsigned* r, unsigned addr) {
    asm volatile("ldmatrix.sync.aligned.m8n8.x4.shared.b16 {%0,%1,%2,%3}, [%4];"
                 : "=r"(r[0]), "=r"(r[1]), "=r"(r[2]), "=r"(r[3]) : "r"(addr));
}
__device__ __forceinline__ void ldsm_x4t(unsigned* r, unsigned addr) {
    asm volatile("ldmatrix.sync.aligned.m8n8.x4.trans.shared.b16 {%0,%1,%2,%3}, [%4];"
                 : "=r"(r[0]), "=r"(r[1]), "=r"(r[2]), "=r"(r[3]) : "r"(addr));
}

__device__ __forceinline__ void cpa16(unsigned dst, const void* src) {
    asm volatile("cp.async.cg.shared.global [%0], [%1], 16;"
                 :: "r"(dst), "l"(src) : "memory");
}
__device__ __forceinline__ void cpa_commit() {
    asm volatile("cp.async.commit_group;" ::: "memory");
}
__device__ __forceinline__ void cpa_wait0() {
    asm volatile("cp.async.wait_group 0;" ::: "memory");
}

__device__ __forceinline__ float sigf(float v) {
    return __fdividef(1.0f, 1.0f + __expf(-v));
}
__device__ __forceinline__ float tanh_fast(float v) {
    return __fdividef(2.0f, 1.0f + __expf(-2.0f * v)) - 1.0f;
}

// Full-grid hierarchical barrier (128 blocks: 16 leaves x 8)
__device__ __forceinline__ void gsyncF(int bid) {
    __syncthreads();
    if (threadIdx.x == 0) {
        volatile unsigned int* genp = &g_gen;
        unsigned int g = *genp;
        __threadfence();
        bool release = false;
        if (atomicAdd(&g_leaf[bid & (NLEAF - 1)], 1u) == (NBLK / NLEAF) - 1u) {
            if (atomicAdd(&g_master, 1u) == NLEAF - 1u) {
                #pragma unroll
                for (int i = 0; i < NLEAF; i++) g_leaf[i] = 0u;
                g_master = 0u;
                __threadfence();
                *genp = g + 1u;
                release = true;
            }
        }
        if (!release) {
            while (*genp == g) { }
        }
    }
    __syncthreads();
}

// Per-group barrier: only the 32 blocks sharing batch-slice mi.
__device__ __forceinline__ void gsyncG(int mi) {
    __syncthreads();
    if (threadIdx.x == 0) {
        volatile unsigned int* genp = &g_ggen[mi * 32];
        unsigned int g = *genp;
        __threadfence();
        if (atomicAdd(&g_gcnt[mi * 32], 1u) == 31u) {
            atomicExch(&g_gcnt[mi * 32], 0u);
            __threadfence();
            *genp = g + 1u;
        } else {
            while (*genp == g) { }
        }
    }
    __syncthreads();
}

// Stage one A chunk (hi & lo) global -> smem via cp.async (4 x 16B per thread)
__device__ __forceinline__ void copy_chunk(unsigned sb, const uint4* Ghi,
                                           const uint4* Glo, int mi, int ck,
                                           int buf, int tid) {
    unsigned dh = sb + OFF_A + (unsigned)((buf * 2 + 0) * ABUF_BYTES);
    unsigned dl = sb + OFF_A + (unsigned)((buf * 2 + 1) * ABUF_BYTES);
    #pragma unroll
    for (int i2 = 0; i2 < 2; i2++) {
        int sl = tid + i2 * THREADS;
        int r = sl >> 4, c = sl & 15;
        int gi = (mi * MB + r) * 64 + ck * 16 + c;   // 64 uint4 per h row
        unsigned doff = (unsigned)(r * 272 + c * 16);
        cpa16(dh + doff, Ghi + gi);
        cpa16(dl + doff, Glo + gi);
    }
}

// ---------- main persistent kernel ----------
extern "C" __global__ void __launch_bounds__(THREADS, 1)
lstm_persist(const float* __restrict__ x, const float* __restrict__ a,
             const float* __restrict__ y,
             const float* __restrict__ W_ih, const float* __restrict__ W_hh,
             const float* __restrict__ b_ih, const float* __restrict__ b_hh,
             const float* __restrict__ W_eta, const float* __restrict__ b_eta,
             const float* __restrict__ W_xi,  const float* __restrict__ b_xi,
             const float* __restrict__ W_zeta, const float* __restrict__ b_zeta,
             float* __restrict__ out) {
    extern __shared__ char smem[];
    __nv_bfloat16* sWhi = (__nv_bfloat16*)(smem + OFF_WHI);
    __nv_bfloat16* sWlo = (__nv_bfloat16*)(smem + OFF_WLO);
    float* swx = (float*)(smem + OFF_P);
    float* swa = swx + 64;
    float* swy = swx + 128;
    float* sbb = swx + 192;
    const unsigned sb = s2u(smem);

    const int tid  = threadIdx.x;
    const int lane = tid & 31;
    const int w    = tid >> 5;       // 16 warps
    const int bid  = blockIdx.x;
    const int mi   = bid >> 5;       // batch slice 0..3
    const int ni   = bid & 31;       // unit slice 0..31
    const int wm   = w & 3;          // m-tile: rows 16*wm .. +15
    const int wn   = w >> 2;         // n-group: cols 16*wn (two 8-wide tiles)

    // ---- W tile into smem, K-MAJOR: sW[k][j], pitch WPITCH bf16 ----
    for (int idx = tid; idx < NG * HID; idx += THREADS) {
        int j = idx >> 9, k = idx & 511;
        int row = (j & 3) * HID + ni * UNITS + (j >> 2); // gate row in W_hh
        float v = W_hh[row * HID + k];
        __nv_bfloat16 hi = __float2bfloat16(v);
        sWhi[k * WPITCH + j] = hi;
        sWlo[k * WPITCH + j] = __float2bfloat16(v - __bfloat162float(hi));
    }
    if (tid < NG) {
        int row = (tid & 3) * HID + ni * UNITS + (tid >> 2);
        swx[tid] = W_ih[row * 3 + 0];
        swa[tid] = W_ih[row * 3 + 1];
        swy[tid] = W_ih[row * 3 + 2];
        sbb[tid] = b_ih[row] + b_hh[row];
    }

    // ---- zero our slice of h (buffer 0) ----
    for (int e = tid; e < MB * UNITS; e += THREADS) {
        int bl = e >> 4, ku = e & 15;
        int gi = (mi * MB + bl) * HID + ni * UNITS + ku;
        g_hhi[0][gi] = __float2bfloat16(0.0f);
        g_hlo[0][gi] = __float2bfloat16(0.0f);
    }
    gsyncG(mi);

    // epilogue ownership
    const bool act = ((lane & 1) == 0);
    const int qr = lane >> 2;
    const int r0 = 16 * wm + qr;            // local batch rows
    const int b0g = mi * MB + r0;
    const int b1g = b0g + 8;
    float cst[2][2] = {{0.f, 0.f}, {0.f, 0.f}};

    // ldmatrix address components (constant per thread)
    const unsigned arow  = (unsigned)((16 * wm + (lane & 15)) * 272);
    const unsigned acol  = (unsigned)((lane >> 4) * 16);
    // B x4.trans: lanes 0-15 -> k-rows 0-15 (n-cols wn*16..+7),
    //             lanes 16-31 -> k-rows 0-15 (n-cols +8)  => regs {nt0, nt0, nt1, nt1}
    const unsigned bbase = (unsigned)((lane & 15) * (WPITCH * 2)
                                      + (16 * wn + ((lane >> 4) & 1) * 8) * 2);

    int cur = 0;
    for (int s = 0; s < T_STEPS; s++) {
        const int t = T_STEPS - 1 - s;

        const uint4* Ghi = (const uint4*)(g_hhi[cur]);
        const uint4* Glo = (const uint4*)(g_hlo[cur]);

        // stage chunk 0 -> buf 0
        copy_chunk(sb, Ghi, Glo, mi, 0, 0, tid);
        cpa_commit();

        // inputs for this step's epilogue (latency hidden under GEMM)
        float x0 = __ldg(&x[t * BATCH + b0g]);
        float a0 = __ldg(&a[t * BATCH + b0g]);
        float y0 = __ldg(&y[t * BATCH + b0g]);
        float x1 = __ldg(&x[t * BATCH + b1g]);
        float a1 = __ldg(&a[t * BATCH + b1g]);
        float y1 = __ldg(&y[t * BATCH + b1g]);

        float acc[2][4] = {{0.f, 0.f, 0.f, 0.f}, {0.f, 0.f, 0.f, 0.f}};

        for (int ck = 0; ck < 4; ck++) {
            cpa_wait0();
            __syncthreads();
            if (ck < 3) {
                copy_chunk(sb, Ghi, Glo, mi, ck + 1, (ck + 1) & 1, tid);
                cpa_commit();
            }

            const unsigned Ahb = sb + OFF_A + ((ck & 1) * 2 + 0) * ABUF_BYTES;
            const unsigned Alb = sb + OFF_A + ((ck & 1) * 2 + 1) * ABUF_BYTES;

            #pragma unroll
            for (int kt = 0; kt < 8; kt++) {
                unsigned ahi[4], alo[4], bhi[4], blo[4];
                unsigned aoff = arow + (unsigned)(kt * 32) + acol;
                ldsm_x4(ahi, Ahb + aoff);
                ldsm_x4(alo, Alb + aoff);
                const unsigned kb = bbase + (unsigned)((ck * 128 + kt * 16) * (WPITCH * 2));
                ldsm_x4t(bhi, sb + OFF_WHI + kb);
                ldsm_x4t(blo, sb + OFF_WLO + kb);
                mma16816(acc[0], ahi, bhi + 0);
                mma16816(acc[1], ahi, bhi + 2);
                mma16816(acc[0], ahi, blo + 0);
                mma16816(acc[1], ahi, blo + 2);
                mma16816(acc[0], alo, bhi + 0);
                mma16816(acc[1], alo, bhi + 2);
            }
        }

        // ---- epilogue: xproj add, fragment exchange, gates, h store ----
        #pragma unroll
        for (int nt = 0; nt < 2; nt++) {
            int ce = 16 * wn + nt * 8 + 2 * (lane & 3);
            int co = ce + 1;
            float wxe = swx[ce], wae = swa[ce], wye = swy[ce], bbe = sbb[ce];
            float wxo = swx[co], wao = swa[co], wyo = swy[co], bbo = sbb[co];
            acc[nt][0] += fmaf(wxe, x0, fmaf(wae, a0, fmaf(wye, y0, bbe)));
            acc[nt][1] += fmaf(wxo, x0, fmaf(wao, a0, fmaf(wyo, y0, bbo)));
            acc[nt][2] += fmaf(wxe, x1, fmaf(wae, a1, fmaf(wye, y1, bbe)));
            acc[nt][3] += fmaf(wxo, x1, fmaf(wao, a1, fmaf(wyo, y1, bbo)));
        }

        float gg[2][4];
        #pragma unroll
        for (int nt = 0; nt < 2; nt++)
            #pragma unroll
            for (int i = 0; i < 4; i++)
                gg[nt][i] = __shfl_xor_sync(0xffffffffu, acc[nt][i], 1);

        if (act) {
            __nv_bfloat16* Hhi = g_hhi[cur ^ 1];
            __nv_bfloat16* Hlo = g_hlo[cur ^ 1];
            #pragma unroll
            for (int nt = 0; nt < 2; nt++) {
                int lu = 4 * wn + nt * 2 + ((lane & 3) >> 1);
                int kg = ni * UNITS + lu;
                #pragma unroll
                for (int rr = 0; rr < 2; rr++) {
                    float iv = acc[nt][2 * rr + 0];
                    float fv = acc[nt][2 * rr + 1];
                    float gv = gg[nt][2 * rr + 0];
                    float ov = gg[nt][2 * rr + 1];
                    float cn = sigf(fv) * cst[nt][rr] + sigf(iv) * tanh_fast(gv);
                    cst[nt][rr] = cn;
                    float h = sigf(ov) * tanh_fast(cn);
                    int bg = rr ? b1g : b0g;
                    __nv_bfloat16 hh = __float2bfloat16(h);
                    Hhi[bg * HID + kg] = hh;
                    Hlo[bg * HID + kg] = __float2bfloat16(h - __bfloat162float(hh));
                }
            }
        }
        gsyncG(mi);         // only our batch-slice group needs to agree
        cur ^= 1;
    }

    // all four groups must finish before heads read the full h
    gsyncF(bid);

    // ---- final heads: reconstruct h = hi + lo ----
    const __nv_bfloat16* Fhi = g_hhi[cur];
    const __nv_bfloat16* Flo = g_hlo[cur];
    const int b = tid;

    // Phase A: zx columns (blocks 0..63), ze logits (blocks 64..79)
    if (b < BATCH) {
        if (bid < 64) {
            const int m = bid;
            float acc = b_xi[m];
            const float* wm_ = W_xi + m * HID;
            #pragma unroll 8
            for (int k = 0; k < HID; k++) {
                float hv = __bfloat162float(Fhi[b * HID + k]) +
                           __bfloat162float(Flo[b * HID + k]);
                acc = fmaf(hv, __ldg(&wm_[k]), acc);
            }
            out[b * 64 + m] = acc;                  // zx: [B][64] at 0
            g_zxT[m * BATCH + b] = acc;
        } else if (bid < 80) {
            const int e = bid - 64;
            float acc = b_eta[e];
            const float* we = W_eta + e * HID;
            #pragma unroll 8
            for (int k = 0; k < HID; k++) {
                float hv = __bfloat162float(Fhi[b * HID + k]) +
                           __bfloat162float(Flo[b * HID + k]);
                acc = fmaf(hv, __ldg(&we[k]), acc);
            }
            g_zeT[e * BATCH + b] = acc;
        }
    }
    gsyncF(bid);

    // Phase B: zy columns (blocks 0..63), ze softmax (block 64)
    if (b < BATCH) {
        if (bid < 64) {
            const int m = bid;
            float acc = b_zeta[m];
            const float* wz = W_zeta + m * (HID + 64);
            #pragma unroll 8
            for (int k = 0; k < HID; k++) {
                float hv = __bfloat162float(Fhi[b * HID + k]) +
                           __bfloat162float(Flo[b * HID + k]);
                acc = fmaf(hv, __ldg(&wz[k]), acc);
            }
            #pragma unroll
            for (int j = 0; j < 64; j++)
                acc = fmaf(g_zxT[j * BATCH + b], __ldg(&wz[HID + j]), acc);
            out[16384 + b * 64 + m] = acc;          // zy: [B][64] at 16384
        } else if (bid == 64) {
            float l[16];
            float mx = -1e30f;
            #pragma unroll
            for (int e = 0; e < 16; e++) {
                l[e] = g_zeT[e * BATCH + b];
                mx = fmaxf(mx, l[e]);
            }
            float ssum = 0.0f;
            #pragma unroll
            for (int e = 0; e < 16; e++) { l[e] = __expf(l[e] - mx); ssum += l[e]; }
            float inv = __fdividef(1.0f, ssum);
            #pragma unroll
            for (int e = 0; e < 16; e++)
                out[32768 + b * 16 + e] = l[e] * inv;   // ze: [B][16] at 32768
        }
    }
}

extern "C" void kernel_launch(void* const* d_in, const int* in_sizes, int n_in,
                              void* d_out, int out_size) {
    const float* x      = (const float*)d_in[0];
    const float* a      = (const float*)d_in[1];
    const float* y      = (const float*)d_in[2];
    const float* W_ih   = (const float*)d_in[3];
    const float* W_hh   = (const float*)d_in[4];
    const float* b_ih   = (const float*)d_in[5];
    const float* b_hh   = (const float*)d_in[6];
    const float* W_eta  = (const float*)d_in[7];
    const float* b_eta  = (const float*)d_in[8];
    const float* W_xi   = (const float*)d_in[9];
    const float* b_xi   = (const float*)d_in[10];
    const float* W_zeta = (const float*)d_in[11];
    const float* b_zeta = (const float*)d_in[12];

    cudaFuncSetAttribute(lstm_persist,
                         cudaFuncAttributeMaxDynamicSharedMemorySize, SMEM_TOTAL);
    lstm_persist<<<NBLK, THREADS, SMEM_TOTAL>>>(
        x, a, y, W_ih, W_hh, b_ih, b_hh,
        W_eta, b_eta, W_xi, b_xi, W_zeta, b_zeta,
        (float*)d_out);
}